// round 4
// baseline (speedup 1.0000x reference)
#include <cuda_runtime.h>
#include <math.h>
#include <float.h>

#define NN 50000
#define NE 800000
#define EPSC 1e-5f

// ---------------- scratch (device globals; no allocation allowed) ----------
__device__ int   g_deg[NN];
__device__ int   g_rowstart[NN + 1];
__device__ int   g_cursor[NN];
__device__ int   g_csr[NE];
__device__ float g_logdeg[NN];
__device__ float g_delta_sum;
__device__ float g_colsum[256];
__device__ float g_colsumsq[256];
__device__ float g_feat[(size_t)NN * 3328];   // max 13*256 features
__device__ float g_hA[(size_t)NN * 256];
__device__ float g_hB[(size_t)NN * 256];

// ---------------- graph preprocessing --------------------------------------
__global__ void k_zero_deg() {
    int i = blockIdx.x * blockDim.x + threadIdx.x;
    if (i < NN) g_deg[i] = 0;
}

__global__ void k_count(const int* __restrict__ dst) {
    int e = blockIdx.x * blockDim.x + threadIdx.x;
    if (e < NE) atomicAdd(&g_deg[dst[e]], 1);
}

// single-block exclusive scan over degrees + log-degree mean numerator
__global__ void k_scan() {
    __shared__ int   sums[1024];
    __shared__ float ls[1024];
    int t = threadIdx.x;
    const int C = (NN + 1023) / 1024;   // 49
    int b = t * C;
    int e = min(b + C, NN);
    int s = 0; float l = 0.f;
    for (int i = b; i < e; i++) {
        int d = g_deg[i];
        s += d;
        l += log1pf((float)d);
    }
    sums[t] = s; ls[t] = l;
    __syncthreads();
    // inclusive scan (Hillis-Steele)
    for (int off = 1; off < 1024; off <<= 1) {
        int v = sums[t];
        if (t >= off) v += sums[t - off];
        __syncthreads();
        sums[t] = v;
        __syncthreads();
    }
    // reduce log-deg sum
    for (int off = 512; off > 0; off >>= 1) {
        if (t < off) ls[t] += ls[t + off];
        __syncthreads();
    }
    if (t == 0) g_delta_sum = ls[0];
    int excl = (t == 0) ? 0 : sums[t - 1];
    for (int i = b; i < e; i++) {
        g_rowstart[i] = excl;
        g_cursor[i]   = excl;
        g_logdeg[i]   = log1pf((float)g_deg[i]);
        excl += g_deg[i];
    }
    if (t == 0) g_rowstart[NN] = NE;
}

__global__ void k_scatter(const int* __restrict__ src, const int* __restrict__ dst) {
    int e = blockIdx.x * blockDim.x + threadIdx.x;
    if (e < NE) {
        int d = dst[e];
        int pos = atomicAdd(&g_cursor[d], 1);
        g_csr[pos] = src[e];
    }
}

// ---------------- PNA aggregation: build feat[N, 13d] ----------------------
// one block per node, one thread per feature column
__global__ void k_aggregate(const float* __restrict__ x, int d) {
    int n = blockIdx.x;
    int f = threadIdx.x;
    int rs = g_rowstart[n], re = g_rowstart[n + 1];
    float sum = 0.f, sq = 0.f, mn = FLT_MAX, mx = -FLT_MAX;
    for (int e = rs; e < re; e++) {
        int s = __ldg(&g_csr[e]);
        float v = __ldg(&x[(size_t)s * d + f]);
        sum += v; sq += v * v;
        mn = fminf(mn, v);
        mx = fmaxf(mx, v);
    }
    float deg  = (float)(re - rs);
    float cnt  = fmaxf(deg, 1.f);
    float mean = sum / cnt;
    float sd   = sqrtf(fmaxf(sq / cnt - mean * mean, 0.f) + EPSC);
    if (deg <= 0.f) { mn = 0.f; mx = 0.f; }
    float ld    = g_logdeg[n];
    float delta = g_delta_sum * (1.0f / NN);
    float amp   = ld / delta;
    float att   = (ld > 0.f) ? delta / fmaxf(ld, 1e-6f) : 1.f;

    size_t base = (size_t)n * 13 * d;
    float xv = __ldg(&x[(size_t)n * d + f]);
    g_feat[base + (size_t)0 * d + f]  = xv;
    g_feat[base + (size_t)1 * d + f]  = mean;
    g_feat[base + (size_t)2 * d + f]  = mn;
    g_feat[base + (size_t)3 * d + f]  = mx;
    g_feat[base + (size_t)4 * d + f]  = sd;
    g_feat[base + (size_t)5 * d + f]  = mean * amp;
    g_feat[base + (size_t)6 * d + f]  = mn * amp;
    g_feat[base + (size_t)7 * d + f]  = mx * amp;
    g_feat[base + (size_t)8 * d + f]  = sd * amp;
    g_feat[base + (size_t)9 * d + f]  = mean * att;
    g_feat[base + (size_t)10 * d + f] = mn * att;
    g_feat[base + (size_t)11 * d + f] = mx * att;
    g_feat[base + (size_t)12 * d + f] = sd * att;
}

// ---------------- fp32 tiled GEMM: C = A[MxK] * B[KxNn] + bias (opt ReLU) --
// BM=64, BN=64, BK=16, 256 threads, 4x4 microtile per thread
__global__ __launch_bounds__(256) void k_gemm(
    const float* __restrict__ A, const float* __restrict__ B,
    const float* __restrict__ bias, float* __restrict__ C,
    int M, int K, int Nn, int relu)
{
    __shared__ float As[16][64];
    __shared__ float Bs[16][64];
    int tid = threadIdx.x;
    int tx = tid % 16, ty = tid / 16;
    int r0 = blockIdx.y * 64;
    int c0 = blockIdx.x * 64;

    float acc[4][4] = {};

    int aRow = tid >> 2;          // 0..63
    int aCol = (tid & 3) << 2;    // 0,4,8,12
    int bRow = tid >> 4;          // 0..15
    int bCol = (tid & 15) << 2;   // 0..60

    for (int k0 = 0; k0 < K; k0 += 16) {
        // A tile (vectorized, K divisible by 16 in all calls)
        if (r0 + aRow < M) {
            float4 v = *reinterpret_cast<const float4*>(&A[(size_t)(r0 + aRow) * K + k0 + aCol]);
            As[aCol + 0][aRow] = v.x;
            As[aCol + 1][aRow] = v.y;
            As[aCol + 2][aRow] = v.z;
            As[aCol + 3][aRow] = v.w;
        } else {
            As[aCol + 0][aRow] = 0.f;
            As[aCol + 1][aRow] = 0.f;
            As[aCol + 2][aRow] = 0.f;
            As[aCol + 3][aRow] = 0.f;
        }
        // B tile (scalar with column guards; Nn=10 case)
        #pragma unroll
        for (int i = 0; i < 4; i++) {
            int col = c0 + bCol + i;
            Bs[bRow][bCol + i] = (col < Nn) ? B[(size_t)(k0 + bRow) * Nn + col] : 0.f;
        }
        __syncthreads();

        #pragma unroll
        for (int k = 0; k < 16; k++) {
            float4 a = *reinterpret_cast<const float4*>(&As[k][ty * 4]);
            float4 b = *reinterpret_cast<const float4*>(&Bs[k][tx * 4]);
            acc[0][0] += a.x * b.x; acc[0][1] += a.x * b.y; acc[0][2] += a.x * b.z; acc[0][3] += a.x * b.w;
            acc[1][0] += a.y * b.x; acc[1][1] += a.y * b.y; acc[1][2] += a.y * b.z; acc[1][3] += a.y * b.w;
            acc[2][0] += a.z * b.x; acc[2][1] += a.z * b.y; acc[2][2] += a.z * b.z; acc[2][3] += a.z * b.w;
            acc[3][0] += a.w * b.x; acc[3][1] += a.w * b.y; acc[3][2] += a.w * b.z; acc[3][3] += a.w * b.w;
        }
        __syncthreads();
    }

    #pragma unroll
    for (int i = 0; i < 4; i++) {
        int row = r0 + ty * 4 + i;
        if (row >= M) continue;
        #pragma unroll
        for (int j = 0; j < 4; j++) {
            int col = c0 + tx * 4 + j;
            if (col < Nn) {
                float v = acc[i][j] + bias[col];
                if (relu) v = fmaxf(v, 0.f);
                C[(size_t)row * Nn + col] = v;
            }
        }
    }
}

// ---------------- batchnorm ------------------------------------------------
__global__ void k_zero_cols() {
    int i = threadIdx.x;
    g_colsum[i] = 0.f;
    g_colsumsq[i] = 0.f;
}

// blockDim = dout, grid = 256 blocks striding rows
__global__ void k_colreduce(const float* __restrict__ h, int dout) {
    int f = threadIdx.x;
    float s = 0.f, ss = 0.f;
    for (int r = blockIdx.x; r < NN; r += gridDim.x) {
        float v = h[(size_t)r * dout + f];
        s += v; ss += v * v;
    }
    atomicAdd(&g_colsum[f], s);
    atomicAdd(&g_colsumsq[f], ss);
}

__global__ void k_bn(float* __restrict__ h, const float* __restrict__ gamma,
                     const float* __restrict__ beta, int dout) {
    int idx = blockIdx.x * blockDim.x + threadIdx.x;
    int total = NN * dout;
    if (idx >= total) return;
    int f = idx % dout;
    float m   = g_colsum[f] * (1.0f / NN);
    float var = fmaxf(g_colsumsq[f] * (1.0f / NN) - m * m, 0.f);
    float v = (h[idx] - m) * rsqrtf(var + EPSC) * gamma[f] + beta[f];
    h[idx] = v;
}

// ---------------- host driver ----------------------------------------------
static void run_layer(const float* x_in, int d, const float* W, const float* b,
                      const float* gamma, const float* beta, int dout,
                      float* feat, float* h_out)
{
    k_aggregate<<<NN, d>>>(x_in, d);
    dim3 grid((dout + 63) / 64, (NN + 63) / 64);
    k_gemm<<<grid, 256>>>(feat, W, b, h_out, NN, 13 * d, dout, 1);
    k_zero_cols<<<1, 256>>>();
    k_colreduce<<<256, dout>>>(h_out, dout);
    int total = NN * dout;
    k_bn<<<(total + 255) / 256, 256>>>(h_out, gamma, beta, dout);
}

extern "C" void kernel_launch(void* const* d_in, const int* in_sizes, int n_in,
                              void* d_out, int out_size)
{
    const float* x  = (const float*)d_in[0];
    const int*   ei = (const int*)d_in[1];
    const float *W1 = (const float*)d_in[2],  *b1 = (const float*)d_in[3];
    const float *g1 = (const float*)d_in[4],  *be1 = (const float*)d_in[5];
    const float *W2 = (const float*)d_in[6],  *b2 = (const float*)d_in[7];
    const float *g2 = (const float*)d_in[8],  *be2 = (const float*)d_in[9];
    const float *W3 = (const float*)d_in[10], *b3 = (const float*)d_in[11];
    const float *g3 = (const float*)d_in[12], *be3 = (const float*)d_in[13];
    const float *W4 = (const float*)d_in[14], *b4 = (const float*)d_in[15];
    const float *g4 = (const float*)d_in[16], *be4 = (const float*)d_in[17];
    const float *Wc = (const float*)d_in[18], *bc = (const float*)d_in[19];

    const int* src = ei;
    const int* dst = ei + NE;

    float *feat, *hA, *hB;
    cudaGetSymbolAddress((void**)&feat, g_feat);
    cudaGetSymbolAddress((void**)&hA,   g_hA);
    cudaGetSymbolAddress((void**)&hB,   g_hB);

    // CSR build
    k_zero_deg<<<(NN + 255) / 256, 256>>>();
    k_count<<<(NE + 255) / 256, 256>>>(dst);
    k_scan<<<1, 1024>>>();
    k_scatter<<<(NE + 255) / 256, 256>>>(src, dst);

    // 4 PNA layers
    run_layer(x,  64,  W1, b1, g1, be1, 128, feat, hA);
    run_layer(hA, 128, W2, b2, g2, be2, 256, feat, hB);
    run_layer(hB, 256, W3, b3, g3, be3, 128, feat, hA);
    run_layer(hA, 128, W4, b4, g4, be4, 64,  feat, hB);

    // classifier
    float* out = (float*)d_out;
    dim3 grid((10 + 63) / 64, (NN + 63) / 64);
    k_gemm<<<grid, 256>>>(hB, Wc, bc, out, NN, 64, 10, 0);
}